// round 2
// baseline (speedup 1.0000x reference)
#include <cuda_runtime.h>

#define N_NODES 100000
#define N_EDGES 1600000
#define KPER 16            // edges per src node (E/N); src[e] = e % N_NODES
#define EPS 1e-5f

// ---------------- device scratch (allowed: __device__ globals) --------------
__device__ float4 g_G[N_NODES * 16];     // G[n][c]  : W_f@feat + W_p@node   (25.6 MB)
__device__ float4 g_P[N_NODES * 16];     // P[n][c]  : W_p@node              (25.6 MB)
__device__ float4 g_Mmax[N_NODES * 16];  // per-node per-channel raw max     (25.6 MB)
__device__ float4 g_Mmin[N_NODES * 16];  // per-node per-channel raw min     (25.6 MB)
__device__ float  g_sum[64];
__device__ float  g_ssq[64];
__device__ float4 g_scale4[16];
__device__ float4 g_shift4[16];

// ---------------------------------------------------------------------------
// K1: per-node transform.  G[n] = W[:, :64] @ feat[n] + W[:, 64:] @ node[n]
//                          P[n] = W[:, 64:] @ node[n]
// block = 256 thr = 4 node-groups x 64 channels; 8 nodes per group -> 32 nodes/block
// ---------------------------------------------------------------------------
__global__ __launch_bounds__(256) void k1_node_transform(
    const float* __restrict__ node,
    const float* __restrict__ features,
    const float* __restrict__ W)
{
    __shared__ float4 wt4[16 * 64];  // wt4[k4*64+c] = W[c][4k4..4k4+3]
    __shared__ float  wp[3 * 64];    // wp[j*64+c]   = W[c][64+j]
    __shared__ float4 f4[32 * 16];   // f4[n*16+k4]
    __shared__ float  xs[32 * 3];

    const int t    = threadIdx.x;
    const int c    = t & 63;
    const int ng   = t >> 6;
    const int base = blockIdx.x * 32;

    if (blockIdx.x == 0 && t < 64) { g_sum[t] = 0.f; g_ssq[t] = 0.f; }

    for (int idx = t; idx < 64 * 16; idx += 256) {
        int cc = idx & 63, k4 = idx >> 6;
        const float* wr = W + cc * 67 + k4 * 4;
        wt4[k4 * 64 + cc] = make_float4(wr[0], wr[1], wr[2], wr[3]);
    }
    for (int idx = t; idx < 64 * 3; idx += 256) {
        int cc = idx & 63, j = idx >> 6;
        wp[j * 64 + cc] = W[cc * 67 + 64 + j];
    }
    const float4* feat4 = (const float4*)features;
    for (int idx = t; idx < 32 * 16; idx += 256) {
        int n = idx >> 4, k4 = idx & 15;
        f4[idx] = feat4[(size_t)(base + n) * 16 + k4];
    }
    for (int idx = t; idx < 32 * 3; idx += 256) {
        xs[idx] = node[(size_t)base * 3 + idx];
    }
    __syncthreads();

    const float w0 = wp[c], w1 = wp[64 + c], w2 = wp[128 + c];
    float p[8], acc[8];
#pragma unroll
    for (int r = 0; r < 8; r++) {
        int nl = ng * 8 + r;
        p[r]   = w0 * xs[nl * 3] + w1 * xs[nl * 3 + 1] + w2 * xs[nl * 3 + 2];
        acc[r] = 0.f;
    }
#pragma unroll
    for (int k4 = 0; k4 < 16; k4++) {
        float4 w = wt4[k4 * 64 + c];
#pragma unroll
        for (int r = 0; r < 8; r++) {
            float4 f = f4[(ng * 8 + r) * 16 + k4];
            acc[r] += w.x * f.x + w.y * f.y + w.z * f.z + w.w * f.w;
        }
    }
    float* Gf = (float*)g_G;
    float* Pf = (float*)g_P;
#pragma unroll
    for (int r = 0; r < 8; r++) {
        int n = base + ng * 8 + r;
        Gf[(size_t)n * 64 + c] = acc[r] + p[r];
        Pf[(size_t)n * 64 + c] = p[r];
    }
}

// ---------------------------------------------------------------------------
// K2: single fused edge pass.  For node i, its 16 edges are e = i + k*N.
//   h[e] = G[dst[e]] - P[i].  Track per-(node,channel) raw max & min, and
//   accumulate per-channel sum / sumsq for the layernorm stats.
// 16 threads per node, float4 channel slice each.
// edges is int32 (JAX x64 disabled: "int64" arrays materialize as int32).
// ---------------------------------------------------------------------------
__device__ __forceinline__ float4 f4sub(float4 a, float4 b) {
    return make_float4(a.x - b.x, a.y - b.y, a.z - b.z, a.w - b.w);
}

__global__ __launch_bounds__(256) void k2_edge_pass(const int* __restrict__ edges)
{
    __shared__ float s_sum[64];
    __shared__ float s_ssq[64];
    const int t = threadIdx.x;
    if (t < 64) { s_sum[t] = 0.f; s_ssq[t] = 0.f; }
    __syncthreads();

    const int gt      = blockIdx.x * 256 + t;
    const int s       = gt & 15;
    const int node0   = gt >> 4;
    const int nstride = (gridDim.x * 256) >> 4;

    float4 sum = make_float4(0, 0, 0, 0);
    float4 ssq = make_float4(0, 0, 0, 0);

    for (int i = node0; i < N_NODES; i += nstride) {
        const float4 p = g_P[(size_t)i * 16 + s];

        int dst0 = edges[2 * i + 1];
        float4 h = f4sub(g_G[(size_t)dst0 * 16 + s], p);
        float4 mx = h, mn = h;
        sum.x += h.x; sum.y += h.y; sum.z += h.z; sum.w += h.w;
        ssq.x += h.x * h.x; ssq.y += h.y * h.y; ssq.z += h.z * h.z; ssq.w += h.w * h.w;

#pragma unroll
        for (int k = 1; k < KPER; k++) {
            int e   = i + k * N_NODES;
            int dst = edges[2 * e + 1];
            float4 g = g_G[(size_t)dst * 16 + s];
            h = f4sub(g, p);
            mx.x = fmaxf(mx.x, h.x); mx.y = fmaxf(mx.y, h.y);
            mx.z = fmaxf(mx.z, h.z); mx.w = fmaxf(mx.w, h.w);
            mn.x = fminf(mn.x, h.x); mn.y = fminf(mn.y, h.y);
            mn.z = fminf(mn.z, h.z); mn.w = fminf(mn.w, h.w);
            sum.x += h.x; sum.y += h.y; sum.z += h.z; sum.w += h.w;
            ssq.x += h.x * h.x; ssq.y += h.y * h.y;
            ssq.z += h.z * h.z; ssq.w += h.w * h.w;
        }
        g_Mmax[(size_t)i * 16 + s] = mx;
        g_Mmin[(size_t)i * 16 + s] = mn;
    }

    atomicAdd(&s_sum[s * 4 + 0], sum.x);
    atomicAdd(&s_sum[s * 4 + 1], sum.y);
    atomicAdd(&s_sum[s * 4 + 2], sum.z);
    atomicAdd(&s_sum[s * 4 + 3], sum.w);
    atomicAdd(&s_ssq[s * 4 + 0], ssq.x);
    atomicAdd(&s_ssq[s * 4 + 1], ssq.y);
    atomicAdd(&s_ssq[s * 4 + 2], ssq.z);
    atomicAdd(&s_ssq[s * 4 + 3], ssq.w);
    __syncthreads();
    if (t < 64) {
        atomicAdd(&g_sum[t], s_sum[t]);
        atomicAdd(&g_ssq[t], s_ssq[t]);
    }
}

// ---------------------------------------------------------------------------
// K3: finalize layernorm constants:  scale = rstd*gamma, shift = beta - mean*scale
// ---------------------------------------------------------------------------
__global__ void k3_stats(const float* __restrict__ gamma, const float* __restrict__ beta)
{
    int c = threadIdx.x;
    float mean = g_sum[c] * (1.0f / N_EDGES);
    float var  = g_ssq[c] * (1.0f / N_EDGES) - mean * mean;
    float rstd = rsqrtf(var + EPS);
    float sc   = rstd * gamma[c];
    ((float*)g_scale4)[c] = sc;
    ((float*)g_shift4)[c] = beta[c] - mean * sc;
}

// ---------------------------------------------------------------------------
// K4: epilogue.  out = relu(scale * (scale>=0 ? Mmax : Mmin) + shift)
// (affine+relu are monotone per sign of scale, so they commute with max_k)
// ---------------------------------------------------------------------------
__global__ __launch_bounds__(256) void k4_out(float* __restrict__ out)
{
    int gt = blockIdx.x * 256 + threadIdx.x;
    if (gt >= N_NODES * 16) return;
    int s = gt & 15;
    float4 sc = g_scale4[s];
    float4 sh = g_shift4[s];
    float4 a  = g_Mmax[gt];
    float4 b  = g_Mmin[gt];
    float4 o;
    o.x = fmaxf(0.f, sc.x * (sc.x >= 0.f ? a.x : b.x) + sh.x);
    o.y = fmaxf(0.f, sc.y * (sc.y >= 0.f ? a.y : b.y) + sh.y);
    o.z = fmaxf(0.f, sc.z * (sc.z >= 0.f ? a.z : b.z) + sh.z);
    o.w = fmaxf(0.f, sc.w * (sc.w >= 0.f ? a.w : b.w) + sh.w);
    ((float4*)out)[gt] = o;
}

// ---------------------------------------------------------------------------
extern "C" void kernel_launch(void* const* d_in, const int* in_sizes, int n_in,
                              void* d_out, int out_size)
{
    const float* node     = (const float*)d_in[0];      // (100000, 3)
    const float* features = (const float*)d_in[1];      // (100000, 64)
    const float* W        = (const float*)d_in[2];      // (64, 67)
    const float* gamma    = (const float*)d_in[3];      // (64,)
    const float* beta     = (const float*)d_in[4];      // (64,)
    const int*   edges    = (const int*)d_in[5];        // (1600000, 2) int32 on device
    float*       out      = (float*)d_out;              // (100000, 64)

    k1_node_transform<<<N_NODES / 32, 256>>>(node, features, W);
    k2_edge_pass<<<(N_NODES * 16) / 256, 256>>>(edges);
    k3_stats<<<1, 64>>>(gamma, beta);
    k4_out<<<(N_NODES * 16) / 256, 256>>>(out);
}

// round 3
// speedup vs baseline: 1.1768x; 1.1768x over previous
#include <cuda_runtime.h>
#include <math_constants.h>

#define N_NODES 100000
#define N_EDGES 1600000
#define KPER 16            // edges per src node; src[e] = e % N_NODES
#define EPS 1e-5f

// ---------------- device scratch (allowed: __device__ globals) --------------
__device__ float4 g_G[N_NODES * 16];   // G[n][c] = W_f@feat[n] + W_p@node[n]  (25.6 MB)
__device__ float4 g_M[N_NODES * 16];   // per-(node,ch) folded extremum q*h    (25.6 MB)
__device__ float  g_sum[64];
__device__ float  g_ssq[64];
__device__ float  g_Wpf[3 * 64];       // W[c][64+j] laid out [j*64+c]
__device__ float  g_sgnf[64];          // sign(gamma[c]) in {+1,-1}
__device__ float4 g_scale4[16];        // rstd*gamma*q  (q folded in)
__device__ float4 g_shift4[16];        // beta - mean*rstd*gamma

// ---------------------------------------------------------------------------
// K1: per-node transform.  G[n] = W[:, :64] @ feat[n] + W[:, 64:] @ node[n]
// block = 256 thr; thread = (channel c, node-group ng); 8 nodes per thread.
// Block 0 additionally publishes Wp rows, sign(gamma), and zeroed stats.
// ---------------------------------------------------------------------------
__global__ __launch_bounds__(256) void k1_node_transform(
    const float* __restrict__ node,
    const float* __restrict__ features,
    const float* __restrict__ W,
    const float* __restrict__ gamma)
{
    __shared__ float4 wt4[16 * 64];  // wt4[k4*64+c] = W[c][4k4..4k4+3]
    __shared__ float  wp[3 * 64];    // wp[j*64+c]   = W[c][64+j]
    __shared__ float4 f4[32 * 16];   // f4[n*16+k4]
    __shared__ float  xs[32 * 3];

    const int t    = threadIdx.x;
    const int c    = t & 63;
    const int ng   = t >> 6;
    const int base = blockIdx.x * 32;

    if (blockIdx.x == 0 && t < 64) {
        g_sum[t]  = 0.f;
        g_ssq[t]  = 0.f;
        g_sgnf[t] = (gamma[t] >= 0.f) ? 1.f : -1.f;
    }
    if (blockIdx.x == 0 && t < 192) {  // g_Wpf[j*64+cc] = W[cc][64+j]
        int j = t >> 6, cc = t & 63;
        g_Wpf[t] = W[cc * 67 + 64 + j];
    }

    for (int idx = t; idx < 64 * 16; idx += 256) {
        int cc = idx & 63, k4 = idx >> 6;
        const float* wr = W + cc * 67 + k4 * 4;
        wt4[k4 * 64 + cc] = make_float4(wr[0], wr[1], wr[2], wr[3]);
    }
    for (int idx = t; idx < 64 * 3; idx += 256) {
        int cc = idx & 63, j = idx >> 6;
        wp[j * 64 + cc] = W[cc * 67 + 64 + j];
    }
    const float4* feat4 = (const float4*)features;
    for (int idx = t; idx < 32 * 16; idx += 256) {
        int n = idx >> 4, k4 = idx & 15;
        f4[idx] = feat4[(size_t)(base + n) * 16 + k4];
    }
    for (int idx = t; idx < 32 * 3; idx += 256) {
        xs[idx] = node[(size_t)base * 3 + idx];
    }
    __syncthreads();

    const float w0 = wp[c], w1 = wp[64 + c], w2 = wp[128 + c];
    float p[8], acc[8];
#pragma unroll
    for (int r = 0; r < 8; r++) {
        int nl = ng * 8 + r;
        p[r]   = w0 * xs[nl * 3] + w1 * xs[nl * 3 + 1] + w2 * xs[nl * 3 + 2];
        acc[r] = 0.f;
    }
#pragma unroll
    for (int k4 = 0; k4 < 16; k4++) {
        float4 w = wt4[k4 * 64 + c];
#pragma unroll
        for (int r = 0; r < 8; r++) {
            float4 f = f4[(ng * 8 + r) * 16 + k4];
            acc[r] += w.x * f.x + w.y * f.y + w.z * f.z + w.w * f.w;
        }
    }
    float* Gf = (float*)g_G;
#pragma unroll
    for (int r = 0; r < 8; r++) {
        int n = base + ng * 8 + r;
        Gf[(size_t)n * 64 + c] = acc[r] + p[r];
    }
}

// ---------------------------------------------------------------------------
// K2: single fused edge pass.  Node i's 16 edges are e = i + k*N.
//   h = G[dst] - Wp@node[i].  Track mx = max_k (q*h)  (q = sign(gamma), so mx
//   is the extremum the final monotone affine+relu needs), plus per-channel
//   sum / sumsq for the layernorm stats.  16 threads per node, float4 slice.
//   Edge dsts are loaded once per (node,k) by one thread and shfl-broadcast.
// ---------------------------------------------------------------------------
__device__ __forceinline__ float4 f4sub(float4 a, float4 b) {
    return make_float4(a.x - b.x, a.y - b.y, a.z - b.z, a.w - b.w);
}

__global__ __launch_bounds__(256) void k2_edge_pass(
    const int* __restrict__ edges,
    const float* __restrict__ node)
{
    __shared__ float s_sum[64];
    __shared__ float s_ssq[64];
    const int t = threadIdx.x;
    if (t < 64) { s_sum[t] = 0.f; s_ssq[t] = 0.f; }
    __syncthreads();

    const int gt   = blockIdx.x * 256 + t;
    const int s    = gt & 15;     // channel slice (4 channels)
    const int i    = gt >> 4;     // node (exactly one per thread at this grid)
    const int lane = t & 31;

    // per-slice constants (channels fixed per thread)
    const float4* Wp4  = (const float4*)g_Wpf;
    const float4* sgn4 = (const float4*)g_sgnf;
    const float4 w0 = Wp4[s];
    const float4 w1 = Wp4[16 + s];
    const float4 w2 = Wp4[32 + s];
    const float4 q  = sgn4[s];

    const float nx = node[3 * i], ny = node[3 * i + 1], nz = node[3 * i + 2];
    float4 p;
    p.x = w0.x * nx + w1.x * ny + w2.x * nz;
    p.y = w0.y * nx + w1.y * ny + w2.y * nz;
    p.z = w0.z * nx + w1.z * ny + w2.z * nz;
    p.w = w0.w * nx + w1.w * ny + w2.w * nz;

    // this thread loads the dst of edge e = i + s*N; k-values shared via shfl
    const int myDst = edges[2 * (i + s * N_NODES) + 1];

    float4 sum = make_float4(0, 0, 0, 0);
    float4 ssq = make_float4(0, 0, 0, 0);
    float4 mx  = make_float4(-CUDART_INF_F, -CUDART_INF_F, -CUDART_INF_F, -CUDART_INF_F);

#pragma unroll
    for (int k = 0; k < KPER; k++) {
        int dst  = __shfl_sync(0xffffffffu, myDst, (lane & 16) | k);
        float4 g = __ldg(&g_G[(size_t)dst * 16 + s]);
        float4 h = f4sub(g, p);
        sum.x += h.x; sum.y += h.y; sum.z += h.z; sum.w += h.w;
        ssq.x += h.x * h.x; ssq.y += h.y * h.y;
        ssq.z += h.z * h.z; ssq.w += h.w * h.w;
        mx.x = fmaxf(mx.x, q.x * h.x);
        mx.y = fmaxf(mx.y, q.y * h.y);
        mx.z = fmaxf(mx.z, q.z * h.z);
        mx.w = fmaxf(mx.w, q.w * h.w);
    }
    g_M[(size_t)i * 16 + s] = mx;

    atomicAdd(&s_sum[s * 4 + 0], sum.x);
    atomicAdd(&s_sum[s * 4 + 1], sum.y);
    atomicAdd(&s_sum[s * 4 + 2], sum.z);
    atomicAdd(&s_sum[s * 4 + 3], sum.w);
    atomicAdd(&s_ssq[s * 4 + 0], ssq.x);
    atomicAdd(&s_ssq[s * 4 + 1], ssq.y);
    atomicAdd(&s_ssq[s * 4 + 2], ssq.z);
    atomicAdd(&s_ssq[s * 4 + 3], ssq.w);
    __syncthreads();
    if (t < 64) {
        atomicAdd(&g_sum[t], s_sum[t]);
        atomicAdd(&g_ssq[t], s_ssq[t]);
    }
}

// ---------------------------------------------------------------------------
// K3: layernorm constants.  scale' = rstd*gamma*q (q folded so K4 uses mx
// directly), shift = beta - mean*rstd*gamma.
// ---------------------------------------------------------------------------
__global__ void k3_stats(const float* __restrict__ gamma, const float* __restrict__ beta)
{
    int c = threadIdx.x;
    float mean = g_sum[c] * (1.0f / N_EDGES);
    float var  = g_ssq[c] * (1.0f / N_EDGES) - mean * mean;
    float rstd = rsqrtf(var + EPS);
    float sc   = rstd * gamma[c];
    ((float*)g_scale4)[c] = sc * g_sgnf[c];
    ((float*)g_shift4)[c] = beta[c] - mean * sc;
}

// ---------------------------------------------------------------------------
// K4: epilogue.  out = relu(scale' * mx + shift)
// ---------------------------------------------------------------------------
__global__ __launch_bounds__(256) void k4_out(float* __restrict__ out)
{
    int gt = blockIdx.x * 256 + threadIdx.x;
    if (gt >= N_NODES * 16) return;
    int s = gt & 15;
    float4 sc = g_scale4[s];
    float4 sh = g_shift4[s];
    float4 m  = g_M[gt];
    float4 o;
    o.x = fmaxf(0.f, sc.x * m.x + sh.x);
    o.y = fmaxf(0.f, sc.y * m.y + sh.y);
    o.z = fmaxf(0.f, sc.z * m.z + sh.z);
    o.w = fmaxf(0.f, sc.w * m.w + sh.w);
    ((float4*)out)[gt] = o;
}

// ---------------------------------------------------------------------------
extern "C" void kernel_launch(void* const* d_in, const int* in_sizes, int n_in,
                              void* d_out, int out_size)
{
    const float* node     = (const float*)d_in[0];      // (100000, 3)
    const float* features = (const float*)d_in[1];      // (100000, 64)
    const float* W        = (const float*)d_in[2];      // (64, 67)
    const float* gamma    = (const float*)d_in[3];      // (64,)
    const float* beta     = (const float*)d_in[4];      // (64,)
    const int*   edges    = (const int*)d_in[5];        // (1600000, 2) int32
    float*       out      = (float*)d_out;              // (100000, 64)

    k1_node_transform<<<N_NODES / 32, 256>>>(node, features, W, gamma);
    k2_edge_pass<<<(N_NODES * 16) / 256, 256>>>(edges, node);
    k3_stats<<<1, 64>>>(gamma, beta);
    k4_out<<<(N_NODES * 16) / 256, 256>>>(out);
}

// round 4
// speedup vs baseline: 1.2683x; 1.0777x over previous
#include <cuda_runtime.h>
#include <math_constants.h>

#define N_NODES 100000
#define N_EDGES 1600000
#define KPER 16            // edges per src node; src[e] = e % N_NODES
#define EPS 1e-5f

// fused edge-pass geometry: 592 blocks x 256 thr, guaranteed co-resident
#define NBLK  592
#define NTHR  256
#define NTOT  (NBLK * NTHR)                       // 151552 threads
#define NSLICE (N_NODES * 16)                     // 1.6M node-channel slices
#define ITERS 11                                  // ceil(NSLICE / NTOT)

// ---------------- device scratch (allowed: __device__ globals) --------------
__device__ float4 g_G[N_NODES * 16];   // G[n][c] = W_f@feat[n] + W_p@node[n] (25.6 MB)
__device__ int    g_dstT[NSLICE];      // dstT[i*16+k] = dst of edge e=i+k*N  (6.4 MB)
__device__ float  g_sum[64];
__device__ float  g_ssq[64];
__device__ float  g_Wpf[3 * 64];       // W[c][64+j] laid out [j*64+c]
__device__ float  g_sgnf[64];          // sign(gamma[c]) in {+1,-1}
__device__ int    g_count;             // zero-init; reset to 0 every launch
__device__ int    g_epoch;             // monotone across launches

// packed f32x2 FMA (sm_103a FFMA2 — PTX-only path)
#define FMA2(d, a, b, c) \
    asm("fma.rn.f32x2 %0, %1, %2, %3;" : "=l"(d) : "l"(a), "l"(b), "l"(c))

// ---------------------------------------------------------------------------
// K0: edge transpose.  g_dstT[i*16+k] = edges[2*(k*N+i)+1], fully coalesced
// both directions via a 16x256 smem tile.
// ---------------------------------------------------------------------------
__global__ __launch_bounds__(256) void k0_transpose(const int* __restrict__ edges)
{
    __shared__ int tile[16][256];
    const int t  = threadIdx.x;
    const int i0 = blockIdx.x * 256;
    const int i  = i0 + t;
    const int2* e2 = (const int2*)edges;

#pragma unroll
    for (int k = 0; k < 16; k++) {
        if (i < N_NODES) tile[k][t] = e2[(size_t)k * N_NODES + i].y;
    }
    __syncthreads();
    if (i < N_NODES) {
        int4* o4 = (int4*)(g_dstT + (size_t)i * 16);
#pragma unroll
        for (int j = 0; j < 4; j++) {
            o4[j] = make_int4(tile[4 * j][t], tile[4 * j + 1][t],
                              tile[4 * j + 2][t], tile[4 * j + 3][t]);
        }
    }
}

// ---------------------------------------------------------------------------
// K1: per-node transform using packed f32x2 FMAs.
//   G[n] = W[:, :64] @ feat[n] + W[:, 64:] @ node[n]
// thread = (channel c, node-group ng); 8 nodes per thread; 32 nodes/block.
// Block 0 additionally publishes Wp rows, sign(gamma), zeroed stats.
// ---------------------------------------------------------------------------
__global__ __launch_bounds__(256) void k1_node_transform(
    const float* __restrict__ node,
    const float* __restrict__ features,
    const float* __restrict__ W,
    const float* __restrict__ gamma)
{
    __shared__ float4 wt4[16 * 64];  // wt4[k4*64+c] = W[c][4k4..4k4+3]
    __shared__ float  wp[3 * 64];    // wp[j*64+c]   = W[c][64+j]
    __shared__ float4 f4[32 * 16];   // f4[n*16+k4]
    __shared__ float  xs[32 * 3];

    const int t    = threadIdx.x;
    const int c    = t & 63;
    const int ng   = t >> 6;
    const int base = blockIdx.x * 32;

    if (blockIdx.x == 0 && t < 64) {
        g_sum[t]  = 0.f;
        g_ssq[t]  = 0.f;
        g_sgnf[t] = (gamma[t] >= 0.f) ? 1.f : -1.f;
    }
    if (blockIdx.x == 0 && t < 192) {  // g_Wpf[j*64+cc] = W[cc][64+j]
        int j = t >> 6, cc = t & 63;
        g_Wpf[t] = W[cc * 67 + 64 + j];
    }

    for (int idx = t; idx < 64 * 16; idx += 256) {
        int cc = idx & 63, k4 = idx >> 6;
        const float* wr = W + cc * 67 + k4 * 4;
        wt4[k4 * 64 + cc] = make_float4(wr[0], wr[1], wr[2], wr[3]);
    }
    for (int idx = t; idx < 64 * 3; idx += 256) {
        int cc = idx & 63, j = idx >> 6;
        wp[j * 64 + cc] = W[cc * 67 + 64 + j];
    }
    const float4* feat4 = (const float4*)features;
    for (int idx = t; idx < 32 * 16; idx += 256) {
        int n = idx >> 4, k4 = idx & 15;
        f4[idx] = feat4[(size_t)(base + n) * 16 + k4];
    }
    for (int idx = t; idx < 32 * 3; idx += 256) {
        xs[idx] = node[(size_t)base * 3 + idx];
    }
    __syncthreads();

    const float w0 = wp[c], w1 = wp[64 + c], w2 = wp[128 + c];
    float p[8];
    unsigned long long acc[8];
#pragma unroll
    for (int r = 0; r < 8; r++) {
        int nl = ng * 8 + r;
        p[r]   = w0 * xs[nl * 3] + w1 * xs[nl * 3 + 1] + w2 * xs[nl * 3 + 2];
        acc[r] = 0ull;   // (+0.0f, +0.0f)
    }
    // float4 in smem == two packed f32x2 values bit-for-bit
    const ulonglong2* wt2 = (const ulonglong2*)wt4;
    const ulonglong2* f2  = (const ulonglong2*)f4;
#pragma unroll
    for (int k4 = 0; k4 < 16; k4++) {
        ulonglong2 w = wt2[k4 * 64 + c];
#pragma unroll
        for (int r = 0; r < 8; r++) {
            ulonglong2 f = f2[(ng * 8 + r) * 16 + k4];
            FMA2(acc[r], w.x, f.x, acc[r]);
            FMA2(acc[r], w.y, f.y, acc[r]);
        }
    }
    float* Gf = (float*)g_G;
#pragma unroll
    for (int r = 0; r < 8; r++) {
        int n = base + ng * 8 + r;
        float lo = __int_as_float((int)(acc[r] & 0xffffffffull));
        float hi = __int_as_float((int)(acc[r] >> 32));
        Gf[(size_t)n * 64 + c] = (lo + hi) + p[r];
    }
}

// ---------------------------------------------------------------------------
// K2: fused edge pass + device-wide barrier + epilogue (one launch).
// Phase A: node i's 16 edges; h = G[dst] - Wp@node[i]; track mx = max_k(q*h)
//          (q = sign(gamma)) in smem; accumulate per-channel sum/ssq.
// Barrier: epoch-based grid sync (all 592 blocks co-resident by construction).
// Phase B: compute scale/shift from stats, write out = relu(sc*mx + sh).
// ---------------------------------------------------------------------------
__device__ __forceinline__ float4 f4sub(float4 a, float4 b) {
    return make_float4(a.x - b.x, a.y - b.y, a.z - b.z, a.w - b.w);
}

__global__ __launch_bounds__(NTHR, 4) void k2_fused(
    const float* __restrict__ node,
    const float* __restrict__ gamma,
    const float* __restrict__ beta,
    float* __restrict__ out)
{
    __shared__ float4 s_mx[ITERS][NTHR];   // 45,056 B
    __shared__ float  s_sum[64], s_ssq[64];
    __shared__ int    s_ep;

    const int t    = threadIdx.x;
    const int gt0  = blockIdx.x * NTHR + t;
    const int lane = t & 31;
    const int s    = gt0 & 15;    // channel slice — invariant under +=NTOT strides

    if (t < 64) { s_sum[t] = 0.f; s_ssq[t] = 0.f; }
    if (t == 0) s_ep = *(volatile int*)&g_epoch;
    __syncthreads();

    // per-slice constants
    const float4 w0 = ((const float4*)g_Wpf)[s];
    const float4 w1 = ((const float4*)g_Wpf)[16 + s];
    const float4 w2 = ((const float4*)g_Wpf)[32 + s];
    const float4 q  = ((const float4*)g_sgnf)[s];

    float4 sum = make_float4(0, 0, 0, 0);
    float4 ssq = make_float4(0, 0, 0, 0);

#pragma unroll
    for (int it = 0; it < ITERS; it++) {
        int gs = gt0 + it * NTOT;
        // NSLICE and NTOT are multiples of 32 -> warps never straddle the
        // boundary; full-mask shfl is safe inside this predicate.
        if (gs < NSLICE) {
            const int i = gs >> 4;
            const float nx = node[3 * i], ny = node[3 * i + 1], nz = node[3 * i + 2];
            float4 p;
            p.x = w0.x * nx + w1.x * ny + w2.x * nz;
            p.y = w0.y * nx + w1.y * ny + w2.y * nz;
            p.z = w0.z * nx + w1.z * ny + w2.z * nz;
            p.w = w0.w * nx + w1.w * ny + w2.w * nz;

            const int myDst = g_dstT[gs];   // coalesced: dstT[i*16+s] == dstT[gs]
            float4 mx = make_float4(-CUDART_INF_F, -CUDART_INF_F,
                                    -CUDART_INF_F, -CUDART_INF_F);
#pragma unroll
            for (int k = 0; k < KPER; k++) {
                int dst  = __shfl_sync(0xffffffffu, myDst, (lane & 16) | k);
                float4 g = __ldg(&g_G[(size_t)dst * 16 + s]);
                float4 h = f4sub(g, p);
                sum.x += h.x; sum.y += h.y; sum.z += h.z; sum.w += h.w;
                ssq.x += h.x * h.x; ssq.y += h.y * h.y;
                ssq.z += h.z * h.z; ssq.w += h.w * h.w;
                mx.x = fmaxf(mx.x, q.x * h.x);
                mx.y = fmaxf(mx.y, q.y * h.y);
                mx.z = fmaxf(mx.z, q.z * h.z);
                mx.w = fmaxf(mx.w, q.w * h.w);
            }
            s_mx[it][t] = mx;
        }
    }

    // block-level stats reduction
    atomicAdd(&s_sum[s * 4 + 0], sum.x);
    atomicAdd(&s_sum[s * 4 + 1], sum.y);
    atomicAdd(&s_sum[s * 4 + 2], sum.z);
    atomicAdd(&s_sum[s * 4 + 3], sum.w);
    atomicAdd(&s_ssq[s * 4 + 0], ssq.x);
    atomicAdd(&s_ssq[s * 4 + 1], ssq.y);
    atomicAdd(&s_ssq[s * 4 + 2], ssq.z);
    atomicAdd(&s_ssq[s * 4 + 3], ssq.w);
    __syncthreads();
    if (t < 64) {
        atomicAdd(&g_sum[t], s_sum[t]);
        atomicAdd(&g_ssq[t], s_ssq[t]);
    }
    __threadfence();      // release: order g_sum/g_ssq adds before the arrive
    __syncthreads();

    // ---- device-wide barrier (epoch / sense-reversal) ----
    if (t == 0) {
        int prev = atomicAdd(&g_count, 1);
        if (prev == NBLK - 1) {
            *(volatile int*)&g_count = 0;
            __threadfence();
            atomicAdd(&g_epoch, 1);
        } else {
            while (*(volatile int*)&g_epoch == s_ep) { }
        }
    }
    __syncthreads();
    __threadfence();      // acquire

    // ---- epilogue: stats -> scale/shift -> output ----
    const int c0 = s * 4;
    float4 sc, sh;
    {
        float g0 = gamma[c0], g1 = gamma[c0 + 1], g2 = gamma[c0 + 2], g3 = gamma[c0 + 3];
        float b0 = beta[c0],  b1 = beta[c0 + 1],  b2 = beta[c0 + 2],  b3 = beta[c0 + 3];
        const float inv = 1.0f / N_EDGES;
#define MKSC(J, GJ, BJ, SCJ, SHJ)                                              \
        {                                                                      \
            float m  = *(volatile float*)&g_sum[c0 + J] * inv;                 \
            float v  = *(volatile float*)&g_ssq[c0 + J] * inv - m * m;         \
            float rs = rsqrtf(v + EPS);                                        \
            SCJ = rs * fabsf(GJ);            /* rstd*gamma*sign(gamma) */      \
            SHJ = BJ - m * rs * GJ;                                            \
        }
        MKSC(0, g0, b0, sc.x, sh.x)
        MKSC(1, g1, b1, sc.y, sh.y)
        MKSC(2, g2, b2, sc.z, sh.z)
        MKSC(3, g3, b3, sc.w, sh.w)
#undef MKSC
    }

    float4* out4 = (float4*)out;
#pragma unroll
    for (int it = 0; it < ITERS; it++) {
        int gs = gt0 + it * NTOT;
        if (gs < NSLICE) {
            float4 m = s_mx[it][t];
            float4 o;
            o.x = fmaxf(0.f, sc.x * m.x + sh.x);
            o.y = fmaxf(0.f, sc.y * m.y + sh.y);
            o.z = fmaxf(0.f, sc.z * m.z + sh.z);
            o.w = fmaxf(0.f, sc.w * m.w + sh.w);
            out4[gs] = o;
        }
    }
}

// ---------------------------------------------------------------------------
extern "C" void kernel_launch(void* const* d_in, const int* in_sizes, int n_in,
                              void* d_out, int out_size)
{
    const float* node     = (const float*)d_in[0];      // (100000, 3)
    const float* features = (const float*)d_in[1];      // (100000, 64)
    const float* W        = (const float*)d_in[2];      // (64, 67)
    const float* gamma    = (const float*)d_in[3];      // (64,)
    const float* beta     = (const float*)d_in[4];      // (64,)
    const int*   edges    = (const int*)d_in[5];        // (1600000, 2) int32
    float*       out      = (float*)d_out;              // (100000, 64)

    k0_transpose<<<(N_NODES + 255) / 256, 256>>>(edges);
    k1_node_transform<<<N_NODES / 32, 256>>>(node, features, W, gamma);
    k2_fused<<<NBLK, NTHR>>>(node, gamma, beta, out);
}